// round 14
// baseline (speedup 1.0000x reference)
#include <cuda_runtime.h>
#include <cuda_bf16.h>
#include <math.h>
#include <stdint.h>

#define N_NODES 50000
#define N_EDGES 800000
#define NF      128
#define D1      256
#define HEADS   16
#define HID     16
#define NG      64
#define NC      10
#define SCAN_BLK ((N_NODES + 1023) / 1024)   // 49

// ---------------- device scratch ----------------
__device__ __nv_bfloat16 g_h1bb[N_NODES * D1];  // post agg1 (bf16, GEMM2 input)
__device__ __nv_bfloat16 g_h1bf[N_NODES * D1];  // layer1 GEMM out (bf16, agg1 gather)
__device__ __nv_bfloat16 g_h2bf[N_NODES * D1];  // layer2 GEMM out (bf16, agg2 gather)
__device__ float g_asrc[N_NODES * HEADS];
__device__ float g_adst[N_NODES * HEADS];
__device__ int   g_deg   [N_NODES];
__device__ int   g_rowptr[N_NODES + 1];
__device__ int   g_cursor[N_NODES];
__device__ int   g_csr_src[N_EDGES];
__device__ int   g_bsum[64];
__device__ float g_pool[NG * HID];
__device__ float g_cnt [NG];

// ---------------- setup kernels ----------------
__global__ void k_zero() {
    int i = blockIdx.x * blockDim.x + threadIdx.x;
    if (i < N_NODES) g_deg[i] = 0;
    if (i < NG * HID) g_pool[i] = 0.f;
    if (i < NG) g_cnt[i] = 0.f;
}

// merged: per-graph node count + edge-dst histogram
__global__ void k_counthist(const int* __restrict__ batch, const int* __restrict__ ei) {
    __shared__ int loc[NG];
    int t = threadIdx.x;
    if (t < NG) loc[t] = 0;
    __syncthreads();
    int i = blockIdx.x * blockDim.x + t;
    if (i < N_NODES) atomicAdd(&loc[batch[i]], 1);
    if (i < N_EDGES) atomicAdd(&g_deg[ei[N_EDGES + i]], 1);
    __syncthreads();
    if (t < NG) { int v = loc[t]; if (v) atomicAdd(&g_cnt[t], (float)v); }
}

__global__ __launch_bounds__(1024) void k_scan1() {
    __shared__ int sh[1024];
    int tid = threadIdx.x;
    int i = blockIdx.x * 1024 + tid;
    int v = (i < N_NODES) ? g_deg[i] : 0;
    sh[tid] = v;
    __syncthreads();
    for (int off = 1; off < 1024; off <<= 1) {
        int t = (tid >= off) ? sh[tid - off] : 0;
        __syncthreads();
        sh[tid] += t;
        __syncthreads();
    }
    if (i < N_NODES) g_rowptr[i] = sh[tid] - v;
    if (tid == 1023) g_bsum[blockIdx.x] = sh[1023];
}

// merged scan2+scan3: every block redundantly reduces its prefix of the 49 block sums
__global__ __launch_bounds__(1024) void k_scan23() {
    __shared__ int red[64];
    int tid = threadIdx.x;
    if (tid < 64) red[tid] = (tid < (int)blockIdx.x && tid < SCAN_BLK) ? g_bsum[tid] : 0;
    __syncthreads();
    for (int s = 32; s > 0; s >>= 1) {
        if (tid < s) red[tid] += red[tid + s];
        __syncthreads();
    }
    int off = red[0];
    int i = blockIdx.x * 1024 + tid;
    if (i < N_NODES) {
        int r = g_rowptr[i] + off;
        g_rowptr[i] = r;
        g_cursor[i] = r;
    }
    if (i == 0) g_rowptr[N_NODES] = N_EDGES;
}

__global__ void k_scatter(const int* __restrict__ ei) {
    int e = blockIdx.x * blockDim.x + threadIdx.x;
    if (e >= N_EDGES) return;
    int s = ei[e];
    int d = ei[N_EDGES + e];
    int p = atomicAdd(&g_cursor[d], 1);
    g_csr_src[p] = s;
}

// ---------------- TF32 tensor-core GEMM + fused attention epilogue ----------------
// C[M x 256] = A[M x K] @ W[K x 256]; A fp32 (ABF16=0) or bf16 (ABF16=1).
// Software-pipelined: next k-chunk prefetched to registers during compute.
#define GBM 128
#define GBN 64
#define GBK 32
#define AS_STRIDE 36
#define BS_STRIDE 36

__device__ __forceinline__ uint32_t f2tf32(float f) {
    uint32_t r;
    asm("cvt.rna.tf32.f32 %0, %1;" : "=r"(r) : "f"(f));
    return r;
}

__device__ __forceinline__ void mma_tf32(float& d0, float& d1, float& d2, float& d3,
                                         uint32_t a0, uint32_t a1, uint32_t a2, uint32_t a3,
                                         uint32_t b0, uint32_t b1) {
    asm volatile(
        "mma.sync.aligned.m16n8k8.row.col.f32.tf32.tf32.f32 "
        "{%0,%1,%2,%3}, {%4,%5,%6,%7}, {%8,%9}, {%0,%1,%2,%3};"
        : "+f"(d0), "+f"(d1), "+f"(d2), "+f"(d3)
        : "r"(a0), "r"(a1), "r"(a2), "r"(a3), "r"(b0), "r"(b1));
}

template <int ABF16>
__global__ __launch_bounds__(256) void k_gemm_attn(const void* __restrict__ Av,
                                                   const float* __restrict__ W,
                                                   __nv_bfloat16* __restrict__ hbf,
                                                   const float* __restrict__ att_s,
                                                   const float* __restrict__ att_d,
                                                   int K) {
    __shared__ uint32_t As[GBM * AS_STRIDE];
    __shared__ uint32_t Bs[GBN * BS_STRIDE];
    const int M = N_NODES;

    int tid = threadIdx.x;
    int warp = tid >> 5, lane = tid & 31;
    int g = lane >> 2, tg = lane & 3;
    int wm = warp & 3;       // 4 m-warps
    int wn = warp >> 2;      // 2 n-warps
    int bm = blockIdx.x * GBM;
    int bn = blockIdx.y * GBN;

    float acc[2][4][4];
#pragma unroll
    for (int mt = 0; mt < 2; mt++)
#pragma unroll
        for (int nt = 0; nt < 4; nt++)
#pragma unroll
            for (int r = 0; r < 4; r++) acc[mt][nt][r] = 0.f;

    // prefetch registers
    float4 ra[4];
    uint4  rab[2];
    float4 rb[2];

    auto load_chunk = [&](int k0) {
        if (ABF16) {
            const __nv_bfloat16* A = (const __nv_bfloat16*)Av;
            int row = tid >> 2, c8 = tid & 3;
#pragma unroll
            for (int p = 0; p < 2; p++) {
                int gr = bm + row + p * 64;
                rab[p] = make_uint4(0u, 0u, 0u, 0u);
                if (gr < M) rab[p] = *(const uint4*)(A + (size_t)gr * K + k0 + c8 * 8);
            }
        } else {
            const float* A = (const float*)Av;
            int row = tid >> 3, c4 = tid & 7;
#pragma unroll
            for (int p = 0; p < 4; p++) {
                int gr = bm + row + p * 32;
                ra[p] = make_float4(0.f, 0.f, 0.f, 0.f);
                if (gr < M) ra[p] = *(const float4*)(A + (size_t)gr * K + k0 + c4 * 4);
            }
        }
        int k = tid >> 4, n4 = tid & 15;
#pragma unroll
        for (int p = 0; p < 2; p++)
            rb[p] = *(const float4*)(W + (size_t)(k0 + k + p * 16) * 256 + bn + n4 * 4);
    };

    auto store_chunk = [&]() {
        if (ABF16) {
            int row = tid >> 2, c8 = tid & 3;
#pragma unroll
            for (int p = 0; p < 2; p++) {
                uint32_t* dst = &As[(row + p * 64) * AS_STRIDE + c8 * 8];
                uint4 v = rab[p];
                dst[0] = v.x << 16; dst[1] = v.x & 0xFFFF0000u;
                dst[2] = v.y << 16; dst[3] = v.y & 0xFFFF0000u;
                dst[4] = v.z << 16; dst[5] = v.z & 0xFFFF0000u;
                dst[6] = v.w << 16; dst[7] = v.w & 0xFFFF0000u;
            }
        } else {
            int row = tid >> 3, c4 = tid & 7;
#pragma unroll
            for (int p = 0; p < 4; p++) {
                uint32_t* dst = &As[(row + p * 32) * AS_STRIDE + c4 * 4];
                float4 v = ra[p];
                dst[0] = f2tf32(v.x); dst[1] = f2tf32(v.y);
                dst[2] = f2tf32(v.z); dst[3] = f2tf32(v.w);
            }
        }
        int k = tid >> 4, n4 = tid & 15;
#pragma unroll
        for (int p = 0; p < 2; p++) {
            int kk = k + p * 16;
            float4 v = rb[p];
            Bs[(n4 * 4 + 0) * BS_STRIDE + kk] = f2tf32(v.x);
            Bs[(n4 * 4 + 1) * BS_STRIDE + kk] = f2tf32(v.y);
            Bs[(n4 * 4 + 2) * BS_STRIDE + kk] = f2tf32(v.z);
            Bs[(n4 * 4 + 3) * BS_STRIDE + kk] = f2tf32(v.w);
        }
    };

    load_chunk(0);
    for (int k0 = 0; k0 < K; k0 += GBK) {
        store_chunk();
        __syncthreads();
        if (k0 + GBK < K) load_chunk(k0 + GBK);   // overlaps with compute below

#pragma unroll
        for (int ks = 0; ks < 4; ks++) {
            int kc = ks * 8 + tg;
            uint32_t af[2][4];
#pragma unroll
            for (int mt = 0; mt < 2; mt++) {
                int r0 = wm * 32 + mt * 16 + g;
                af[mt][0] = As[r0 * AS_STRIDE + kc];
                af[mt][1] = As[(r0 + 8) * AS_STRIDE + kc];
                af[mt][2] = As[r0 * AS_STRIDE + kc + 4];
                af[mt][3] = As[(r0 + 8) * AS_STRIDE + kc + 4];
            }
            uint32_t bf[4][2];
#pragma unroll
            for (int nt = 0; nt < 4; nt++) {
                int nb = wn * 32 + nt * 8 + g;
                bf[nt][0] = Bs[nb * BS_STRIDE + kc];
                bf[nt][1] = Bs[nb * BS_STRIDE + kc + 4];
            }
#pragma unroll
            for (int mt = 0; mt < 2; mt++)
#pragma unroll
                for (int nt = 0; nt < 4; nt++)
                    mma_tf32(acc[mt][nt][0], acc[mt][nt][1], acc[mt][nt][2], acc[mt][nt][3],
                             af[mt][0], af[mt][1], af[mt][2], af[mt][3],
                             bf[nt][0], bf[nt][1]);
        }
        __syncthreads();
    }

    // ---- fused epilogue: bf16 store + attention dots ----
    int hg0 = (bn + wn * 32) >> 4;
    float asl[2][4], adl[2][4];
#pragma unroll
    for (int hs = 0; hs < 2; hs++) {
        int hb = (hg0 + hs) * 16;
        asl[hs][0] = __ldg(att_s + hb + 2 * tg);
        asl[hs][1] = __ldg(att_s + hb + 2 * tg + 1);
        asl[hs][2] = __ldg(att_s + hb + 8 + 2 * tg);
        asl[hs][3] = __ldg(att_s + hb + 9 + 2 * tg);
        adl[hs][0] = __ldg(att_d + hb + 2 * tg);
        adl[hs][1] = __ldg(att_d + hb + 2 * tg + 1);
        adl[hs][2] = __ldg(att_d + hb + 8 + 2 * tg);
        adl[hs][3] = __ldg(att_d + hb + 9 + 2 * tg);
    }

#pragma unroll
    for (int mt = 0; mt < 2; mt++) {
#pragma unroll
        for (int rh = 0; rh < 2; rh++) {
            int row = bm + wm * 32 + mt * 16 + g + rh * 8;
            int a0 = rh * 2, a1 = rh * 2 + 1;
            if (row < M) {
                __nv_bfloat16* hrow = hbf + (size_t)row * 256 + bn + wn * 32 + 2 * tg;
#pragma unroll
                for (int nt = 0; nt < 4; nt++) {
                    __nv_bfloat162 b2 = __float22bfloat162_rn(
                        make_float2(acc[mt][nt][a0], acc[mt][nt][a1]));
                    *(__nv_bfloat162*)(hrow + nt * 8) = b2;
                }
            }
#pragma unroll
            for (int hs = 0; hs < 2; hs++) {
                float s = acc[mt][2 * hs][a0]     * asl[hs][0]
                        + acc[mt][2 * hs][a1]     * asl[hs][1]
                        + acc[mt][2 * hs + 1][a0] * asl[hs][2]
                        + acc[mt][2 * hs + 1][a1] * asl[hs][3];
                float d = acc[mt][2 * hs][a0]     * adl[hs][0]
                        + acc[mt][2 * hs][a1]     * adl[hs][1]
                        + acc[mt][2 * hs + 1][a0] * adl[hs][2]
                        + acc[mt][2 * hs + 1][a1] * adl[hs][3];
                s += __shfl_xor_sync(0xffffffffu, s, 1);
                s += __shfl_xor_sync(0xffffffffu, s, 2);
                d += __shfl_xor_sync(0xffffffffu, d, 1);
                d += __shfl_xor_sync(0xffffffffu, d, 2);
                if (tg == 0 && row < M) {
                    g_asrc[row * 16 + hg0 + hs] = s;
                    g_adst[row * 16 + hg0 + hs] = d;
                }
            }
        }
    }
}

// ---------------- single-pass aggregation helpers ----------------
__device__ __forceinline__ float lrelu02(float x) { return (x > 0.f) ? x : 0.2f * x; }

__device__ __forceinline__ void acc_bf16(float o[8], float al, uint4 pv) {
    float2 f0 = __bfloat1622float2(*(__nv_bfloat162*)&pv.x);
    float2 f1 = __bfloat1622float2(*(__nv_bfloat162*)&pv.y);
    float2 f2 = __bfloat1622float2(*(__nv_bfloat162*)&pv.z);
    float2 f3 = __bfloat1622float2(*(__nv_bfloat162*)&pv.w);
    o[0] += al * f0.x; o[1] += al * f0.y;
    o[2] += al * f1.x; o[3] += al * f1.y;
    o[4] += al * f2.x; o[5] += al * f2.y;
    o[6] += al * f3.x; o[7] += al * f3.y;
}

// ---------------- layer-1 aggregation: warp/node, single pass, unroll-8 ----------------
__global__ __launch_bounds__(256) void k_agg1(const float* __restrict__ bias,
                                              const float* __restrict__ gm,
                                              const float* __restrict__ bt,
                                              const float* __restrict__ mn,
                                              const float* __restrict__ vr) {
    int warp = (blockIdx.x * blockDim.x + threadIdx.x) >> 5;
    int lane = threadIdx.x & 31;
    if (warp >= N_NODES) return;
    int n = warp;
    int h = lane >> 1;
    int half = lane & 1;

    float adn = g_adst[n * 16 + h];
    int jb = g_rowptr[n], je = g_rowptr[n + 1];

    const uint4* hbase = (const uint4*)g_h1bf;
    int voff = h * 2 + half;

    float o[8] = {0.f, 0.f, 0.f, 0.f, 0.f, 0.f, 0.f, 0.f};
    float e0 = __expf(lrelu02(g_asrc[n * 16 + h] + adn));
    float denom = e0;
    acc_bf16(o, e0, hbase[(size_t)n * 32 + voff]);

    int j = jb;
    for (; j + 8 <= je; j += 8) {
        int u[8];
#pragma unroll
        for (int q = 0; q < 8; q++) u[q] = g_csr_src[j + q];
        float x[8];
#pragma unroll
        for (int q = 0; q < 8; q++) x[q] = g_asrc[u[q] * 16 + h];
        uint4 p[8];
#pragma unroll
        for (int q = 0; q < 8; q++) p[q] = hbase[(size_t)u[q] * 32 + voff];
        float a[8];
#pragma unroll
        for (int q = 0; q < 8; q++) { a[q] = __expf(lrelu02(x[q] + adn)); denom += a[q]; }
#pragma unroll
        for (int q = 0; q < 8; q++) acc_bf16(o, a[q], p[q]);
    }
    for (; j + 4 <= je; j += 4) {
        int u0 = g_csr_src[j],     u1 = g_csr_src[j + 1];
        int u2 = g_csr_src[j + 2], u3 = g_csr_src[j + 3];
        float x0 = g_asrc[u0 * 16 + h], x1 = g_asrc[u1 * 16 + h];
        float x2 = g_asrc[u2 * 16 + h], x3 = g_asrc[u3 * 16 + h];
        uint4 p0 = hbase[(size_t)u0 * 32 + voff], p1 = hbase[(size_t)u1 * 32 + voff];
        uint4 p2 = hbase[(size_t)u2 * 32 + voff], p3 = hbase[(size_t)u3 * 32 + voff];
        float a0 = __expf(lrelu02(x0 + adn));
        float a1 = __expf(lrelu02(x1 + adn));
        float a2 = __expf(lrelu02(x2 + adn));
        float a3 = __expf(lrelu02(x3 + adn));
        denom += (a0 + a1) + (a2 + a3);
        acc_bf16(o, a0, p0); acc_bf16(o, a1, p1);
        acc_bf16(o, a2, p2); acc_bf16(o, a3, p3);
    }
    for (; j < je; j++) {
        int u = g_csr_src[j];
        float a = __expf(lrelu02(g_asrc[u * 16 + h] + adn));
        denom += a;
        acc_bf16(o, a, hbase[(size_t)u * 32 + voff]);
    }

    float invs = 1.f / (denom + 1e-16f);
    int idx = lane * 8;
#pragma unroll
    for (int t = 0; t < 8; t++) {
        int c = idx + t;
        float v = o[t] * invs + bias[c];
        v = (v > 0.f) ? v : (__expf(v) - 1.f);
        v = (v - mn[c]) * (gm[c] * rsqrtf(vr[c] + 1e-5f)) + bt[c];
        o[t] = v;
    }
    uint32_t pk[4];
#pragma unroll
    for (int t = 0; t < 4; t++) {
        __nv_bfloat162 b2 = __float22bfloat162_rn(make_float2(o[2 * t], o[2 * t + 1]));
        pk[t] = *(uint32_t*)&b2;
    }
    *(uint4*)(g_h1bb + (size_t)n * 256 + idx) = make_uint4(pk[0], pk[1], pk[2], pk[3]);
}

// ---------------- layer-2 aggregation: single pass + head-mean + bn2 + pooling ----------------
__global__ __launch_bounds__(256) void k_agg2(const int* __restrict__ batch,
                                              const float* __restrict__ bias,
                                              const float* __restrict__ gm,
                                              const float* __restrict__ bt,
                                              const float* __restrict__ mn,
                                              const float* __restrict__ vr) {
    int warp = (blockIdx.x * blockDim.x + threadIdx.x) >> 5;
    int lane = threadIdx.x & 31;
    if (warp >= N_NODES) return;
    int n = warp;
    int h = lane >> 1;
    int half = lane & 1;

    float adn = g_adst[n * 16 + h];
    int jb = g_rowptr[n], je = g_rowptr[n + 1];

    const uint4* hbase = (const uint4*)g_h2bf;
    int voff = h * 2 + half;

    float o[8] = {0.f, 0.f, 0.f, 0.f, 0.f, 0.f, 0.f, 0.f};
    float e0 = __expf(lrelu02(g_asrc[n * 16 + h] + adn));
    float denom = e0;
    acc_bf16(o, e0, hbase[(size_t)n * 32 + voff]);

    int j = jb;
    for (; j + 8 <= je; j += 8) {
        int u[8];
#pragma unroll
        for (int q = 0; q < 8; q++) u[q] = g_csr_src[j + q];
        float x[8];
#pragma unroll
        for (int q = 0; q < 8; q++) x[q] = g_asrc[u[q] * 16 + h];
        uint4 p[8];
#pragma unroll
        for (int q = 0; q < 8; q++) p[q] = hbase[(size_t)u[q] * 32 + voff];
        float a[8];
#pragma unroll
        for (int q = 0; q < 8; q++) { a[q] = __expf(lrelu02(x[q] + adn)); denom += a[q]; }
#pragma unroll
        for (int q = 0; q < 8; q++) acc_bf16(o, a[q], p[q]);
    }
    for (; j + 4 <= je; j += 4) {
        int u0 = g_csr_src[j],     u1 = g_csr_src[j + 1];
        int u2 = g_csr_src[j + 2], u3 = g_csr_src[j + 3];
        float x0 = g_asrc[u0 * 16 + h], x1 = g_asrc[u1 * 16 + h];
        float x2 = g_asrc[u2 * 16 + h], x3 = g_asrc[u3 * 16 + h];
        uint4 p0 = hbase[(size_t)u0 * 32 + voff], p1 = hbase[(size_t)u1 * 32 + voff];
        uint4 p2 = hbase[(size_t)u2 * 32 + voff], p3 = hbase[(size_t)u3 * 32 + voff];
        float a0 = __expf(lrelu02(x0 + adn));
        float a1 = __expf(lrelu02(x1 + adn));
        float a2 = __expf(lrelu02(x2 + adn));
        float a3 = __expf(lrelu02(x3 + adn));
        denom += (a0 + a1) + (a2 + a3);
        acc_bf16(o, a0, p0); acc_bf16(o, a1, p1);
        acc_bf16(o, a2, p2); acc_bf16(o, a3, p3);
    }
    for (; j < je; j++) {
        int u = g_csr_src[j];
        float a = __expf(lrelu02(g_asrc[u * 16 + h] + adn));
        denom += a;
        acc_bf16(o, a, hbase[(size_t)u * 32 + voff]);
    }

    float invs = 1.f / (denom + 1e-16f);
#pragma unroll
    for (int t = 0; t < 8; t++) o[t] *= invs;

#pragma unroll
    for (int t = 0; t < 8; t++) {
        float v = o[t];
        v += __shfl_xor_sync(0xffffffffu, v, 2);
        v += __shfl_xor_sync(0xffffffffu, v, 4);
        v += __shfl_xor_sync(0xffffffffu, v, 8);
        v += __shfl_xor_sync(0xffffffffu, v, 16);
        o[t] = v;
    }
    if (lane < 2) {
#pragma unroll
        for (int t = 0; t < 8; t++) {
            int c = lane * 8 + t;
            float v = o[t] * (1.f / 16.f) + bias[c];
            v = (v - mn[c]) * (gm[c] * rsqrtf(vr[c] + 1e-5f)) + bt[c];
            o[t] = v;
        }
        int gidx = batch[n];
        float* p = g_pool + gidx * 16 + lane * 8;
        asm volatile("red.global.add.v4.f32 [%0], {%1,%2,%3,%4};"
                     :: "l"(p), "f"(o[0]), "f"(o[1]), "f"(o[2]), "f"(o[3]) : "memory");
        asm volatile("red.global.add.v4.f32 [%0], {%1,%2,%3,%4};"
                     :: "l"(p + 4), "f"(o[4]), "f"(o[5]), "f"(o[6]), "f"(o[7]) : "memory");
    }
}

// ---------------- classifier ----------------
__global__ void k_final(const float* __restrict__ linW,
                        const float* __restrict__ linb,
                        float* __restrict__ out) {
    int tid = threadIdx.x;
    if (tid >= NG * NC) return;
    int g = tid / NC, k = tid % NC;
    float cg = fmaxf(g_cnt[g], 1.f);
    float acc = linb[k];
#pragma unroll
    for (int c = 0; c < HID; c++)
        acc += (g_pool[g * 16 + c] / cg) * linW[c * NC + k];
    out[g * NC + k] = acc;
}

// ---------------- launch ----------------
extern "C" void kernel_launch(void* const* d_in, const int* in_sizes, int n_in,
                              void* d_out, int out_size) {
    const float* x        = (const float*)d_in[0];
    const int*   ei       = (const int*)  d_in[1];
    const int*   batch    = (const int*)  d_in[2];
    const float* W1       = (const float*)d_in[3];
    const float* att_src1 = (const float*)d_in[4];
    const float* att_dst1 = (const float*)d_in[5];
    const float* bias1    = (const float*)d_in[6];
    const float* bn1_g    = (const float*)d_in[7];
    const float* bn1_b    = (const float*)d_in[8];
    const float* bn1_m    = (const float*)d_in[9];
    const float* bn1_v    = (const float*)d_in[10];
    const float* W2       = (const float*)d_in[11];
    const float* att_src2 = (const float*)d_in[12];
    const float* att_dst2 = (const float*)d_in[13];
    const float* bias2    = (const float*)d_in[14];
    const float* bn2_g    = (const float*)d_in[15];
    const float* bn2_b    = (const float*)d_in[16];
    const float* bn2_m    = (const float*)d_in[17];
    const float* bn2_v    = (const float*)d_in[18];
    const float* linW     = (const float*)d_in[19];
    const float* linb     = (const float*)d_in[20];
    float* out = (float*)d_out;

    __nv_bfloat16* d_h1bb; cudaGetSymbolAddress((void**)&d_h1bb, g_h1bb);
    __nv_bfloat16* d_h1bf; cudaGetSymbolAddress((void**)&d_h1bf, g_h1bf);
    __nv_bfloat16* d_h2bf; cudaGetSymbolAddress((void**)&d_h2bf, g_h2bf);

    static cudaStream_t s_side = nullptr;
    static cudaEvent_t ev_fork = nullptr, ev_join = nullptr;
    if (s_side == nullptr) {
        cudaStreamCreateWithFlags(&s_side, cudaStreamNonBlocking);
        cudaEventCreateWithFlags(&ev_fork, cudaEventDisableTiming);
        cudaEventCreateWithFlags(&ev_join, cudaEventDisableTiming);
    }

    cudaEventRecord(ev_fork, 0);
    cudaStreamWaitEvent(s_side, ev_fork, 0);

    // CSR build on side stream (5 launches; overlaps gemm1 on main stream)
    k_zero     <<<(N_NODES + 255) / 256, 256, 0, s_side>>>();
    k_counthist<<<(N_EDGES + 255) / 256, 256, 0, s_side>>>(batch, ei);
    k_scan1    <<<SCAN_BLK, 1024, 0, s_side>>>();
    k_scan23   <<<SCAN_BLK, 1024, 0, s_side>>>();
    k_scatter  <<<(N_EDGES + 255) / 256, 256, 0, s_side>>>(ei);
    cudaEventRecord(ev_join, s_side);

    dim3 ggrid((N_NODES + GBM - 1) / GBM, 256 / GBN);

    // layer 1 (GEMM + fused attn) — launch slot #6 for ncu capture
    k_gemm_attn<0><<<ggrid, 256>>>(x, W1, d_h1bf, att_src1, att_dst1, NF);

    cudaStreamWaitEvent(0, ev_join, 0);

    k_agg1<<<(N_NODES * 32 + 255) / 256, 256>>>(bias1, bn1_g, bn1_b, bn1_m, bn1_v);

    // layer 2 (bf16 A input)
    k_gemm_attn<1><<<ggrid, 256>>>(d_h1bb, W2, d_h2bf, att_src2, att_dst2, D1);
    k_agg2<<<(N_NODES * 32 + 255) / 256, 256>>>(batch, bias2, bn2_g, bn2_b, bn2_m, bn2_v);

    k_final<<<1, NG * NC>>>(linW, linb, out);
}

// round 15
// speedup vs baseline: 1.0194x; 1.0194x over previous
#include <cuda_runtime.h>
#include <cuda_bf16.h>
#include <math.h>
#include <stdint.h>

#define N_NODES 50000
#define N_EDGES 800000
#define NF      128
#define D1      256
#define HEADS   16
#define HID     16
#define NG      64
#define NC      10
#define SCAN_BLK ((N_NODES + 1023) / 1024)   // 49

// ---------------- device scratch ----------------
__device__ __nv_bfloat16 g_h1bb[N_NODES * D1];  // post agg1 (bf16, GEMM2 input)
__device__ __nv_bfloat16 g_h1bf[N_NODES * D1];  // layer1 GEMM out (bf16, agg1 gather)
__device__ __nv_bfloat16 g_h2bf[N_NODES * D1];  // layer2 GEMM out (bf16, agg2 gather)
__device__ float g_asrc[N_NODES * HEADS];
__device__ float g_adst[N_NODES * HEADS];
__device__ int   g_deg   [N_NODES];
__device__ int   g_rowptr[N_NODES + 1];
__device__ int   g_cursor[N_NODES];
__device__ int   g_csr_src[N_EDGES];
__device__ int   g_bsum[64];
__device__ float g_pool[NG * HID];
__device__ float g_cnt [NG];

// ---------------- setup kernels ----------------
__global__ void k_zero() {
    int i = blockIdx.x * blockDim.x + threadIdx.x;
    if (i < N_NODES) g_deg[i] = 0;
    if (i < NG * HID) g_pool[i] = 0.f;
    if (i < NG) g_cnt[i] = 0.f;
}

// merged: per-graph node count + edge-dst histogram
__global__ void k_counthist(const int* __restrict__ batch, const int* __restrict__ ei) {
    __shared__ int loc[NG];
    int t = threadIdx.x;
    if (t < NG) loc[t] = 0;
    __syncthreads();
    int i = blockIdx.x * blockDim.x + t;
    if (i < N_NODES) atomicAdd(&loc[batch[i]], 1);
    if (i < N_EDGES) atomicAdd(&g_deg[ei[N_EDGES + i]], 1);
    __syncthreads();
    if (t < NG) { int v = loc[t]; if (v) atomicAdd(&g_cnt[t], (float)v); }
}

__global__ __launch_bounds__(1024) void k_scan1() {
    __shared__ int sh[1024];
    int tid = threadIdx.x;
    int i = blockIdx.x * 1024 + tid;
    int v = (i < N_NODES) ? g_deg[i] : 0;
    sh[tid] = v;
    __syncthreads();
    for (int off = 1; off < 1024; off <<= 1) {
        int t = (tid >= off) ? sh[tid - off] : 0;
        __syncthreads();
        sh[tid] += t;
        __syncthreads();
    }
    if (i < N_NODES) g_rowptr[i] = sh[tid] - v;
    if (tid == 1023) g_bsum[blockIdx.x] = sh[1023];
}

// merged scan2+scan3: every block redundantly reduces its prefix of the 49 block sums
__global__ __launch_bounds__(1024) void k_scan23() {
    __shared__ int red[64];
    int tid = threadIdx.x;
    if (tid < 64) red[tid] = (tid < (int)blockIdx.x && tid < SCAN_BLK) ? g_bsum[tid] : 0;
    __syncthreads();
    for (int s = 32; s > 0; s >>= 1) {
        if (tid < s) red[tid] += red[tid + s];
        __syncthreads();
    }
    int off = red[0];
    int i = blockIdx.x * 1024 + tid;
    if (i < N_NODES) {
        int r = g_rowptr[i] + off;
        g_rowptr[i] = r;
        g_cursor[i] = r;
    }
    if (i == 0) g_rowptr[N_NODES] = N_EDGES;
}

__global__ void k_scatter(const int* __restrict__ ei) {
    int e = blockIdx.x * blockDim.x + threadIdx.x;
    if (e >= N_EDGES) return;
    int s = ei[e];
    int d = ei[N_EDGES + e];
    int p = atomicAdd(&g_cursor[d], 1);
    g_csr_src[p] = s;
}

// ---------------- TF32 tensor-core GEMM + fused attention epilogue (R13 form) ----------------
#define GBM 128
#define GBN 64
#define GBK 32
#define AS_STRIDE 36
#define BS_STRIDE 36

__device__ __forceinline__ uint32_t f2tf32(float f) {
    uint32_t r;
    asm("cvt.rna.tf32.f32 %0, %1;" : "=r"(r) : "f"(f));
    return r;
}

__device__ __forceinline__ void mma_tf32(float& d0, float& d1, float& d2, float& d3,
                                         uint32_t a0, uint32_t a1, uint32_t a2, uint32_t a3,
                                         uint32_t b0, uint32_t b1) {
    asm volatile(
        "mma.sync.aligned.m16n8k8.row.col.f32.tf32.tf32.f32 "
        "{%0,%1,%2,%3}, {%4,%5,%6,%7}, {%8,%9}, {%0,%1,%2,%3};"
        : "+f"(d0), "+f"(d1), "+f"(d2), "+f"(d3)
        : "r"(a0), "r"(a1), "r"(a2), "r"(a3), "r"(b0), "r"(b1));
}

template <int ABF16>
__global__ __launch_bounds__(256) void k_gemm_attn(const void* __restrict__ Av,
                                                   const float* __restrict__ W,
                                                   __nv_bfloat16* __restrict__ hbf,
                                                   const float* __restrict__ att_s,
                                                   const float* __restrict__ att_d,
                                                   int K) {
    __shared__ uint32_t As[GBM * AS_STRIDE];
    __shared__ uint32_t Bs[GBN * BS_STRIDE];
    const int M = N_NODES;

    int tid = threadIdx.x;
    int warp = tid >> 5, lane = tid & 31;
    int g = lane >> 2, tg = lane & 3;
    int wm = warp & 3;       // 4 m-warps
    int wn = warp >> 2;      // 2 n-warps
    int bm = blockIdx.x * GBM;
    int bn = blockIdx.y * GBN;

    float acc[2][4][4];
#pragma unroll
    for (int mt = 0; mt < 2; mt++)
#pragma unroll
        for (int nt = 0; nt < 4; nt++)
#pragma unroll
            for (int r = 0; r < 4; r++) acc[mt][nt][r] = 0.f;

    for (int k0 = 0; k0 < K; k0 += GBK) {
        if (ABF16) {
            const __nv_bfloat16* A = (const __nv_bfloat16*)Av;
            int row = tid >> 2;        // 0..63
            int c8 = tid & 3;          // 0..3
#pragma unroll
            for (int p = 0; p < 2; p++) {
                int r = row + p * 64;
                int gr = bm + r;
                uint4 v = make_uint4(0u, 0u, 0u, 0u);
                if (gr < M) v = *(const uint4*)(A + (size_t)gr * K + k0 + c8 * 8);
                uint32_t* dst = &As[r * AS_STRIDE + c8 * 8];
                dst[0] = v.x << 16; dst[1] = v.x & 0xFFFF0000u;
                dst[2] = v.y << 16; dst[3] = v.y & 0xFFFF0000u;
                dst[4] = v.z << 16; dst[5] = v.z & 0xFFFF0000u;
                dst[6] = v.w << 16; dst[7] = v.w & 0xFFFF0000u;
            }
        } else {
            const float* A = (const float*)Av;
            int row = tid >> 3;        // 0..31
            int c4 = tid & 7;          // 0..7
#pragma unroll
            for (int p = 0; p < 4; p++) {
                int r = row + p * 32;
                int gr = bm + r;
                float4 v = make_float4(0.f, 0.f, 0.f, 0.f);
                if (gr < M) v = *(const float4*)(A + (size_t)gr * K + k0 + c4 * 4);
                uint32_t* dst = &As[r * AS_STRIDE + c4 * 4];
                dst[0] = f2tf32(v.x); dst[1] = f2tf32(v.y);
                dst[2] = f2tf32(v.z); dst[3] = f2tf32(v.w);
            }
        }
        {
            int k = tid >> 4;
            int n4 = tid & 15;
#pragma unroll
            for (int p = 0; p < 2; p++) {
                int kk = k + p * 16;
                float4 v = *(const float4*)(W + (size_t)(k0 + kk) * 256 + bn + n4 * 4);
                Bs[(n4 * 4 + 0) * BS_STRIDE + kk] = f2tf32(v.x);
                Bs[(n4 * 4 + 1) * BS_STRIDE + kk] = f2tf32(v.y);
                Bs[(n4 * 4 + 2) * BS_STRIDE + kk] = f2tf32(v.z);
                Bs[(n4 * 4 + 3) * BS_STRIDE + kk] = f2tf32(v.w);
            }
        }
        __syncthreads();

#pragma unroll
        for (int ks = 0; ks < 4; ks++) {
            int kc = ks * 8 + tg;
            uint32_t af[2][4];
#pragma unroll
            for (int mt = 0; mt < 2; mt++) {
                int r0 = wm * 32 + mt * 16 + g;
                af[mt][0] = As[r0 * AS_STRIDE + kc];
                af[mt][1] = As[(r0 + 8) * AS_STRIDE + kc];
                af[mt][2] = As[r0 * AS_STRIDE + kc + 4];
                af[mt][3] = As[(r0 + 8) * AS_STRIDE + kc + 4];
            }
            uint32_t bf[4][2];
#pragma unroll
            for (int nt = 0; nt < 4; nt++) {
                int nb = wn * 32 + nt * 8 + g;
                bf[nt][0] = Bs[nb * BS_STRIDE + kc];
                bf[nt][1] = Bs[nb * BS_STRIDE + kc + 4];
            }
#pragma unroll
            for (int mt = 0; mt < 2; mt++)
#pragma unroll
                for (int nt = 0; nt < 4; nt++)
                    mma_tf32(acc[mt][nt][0], acc[mt][nt][1], acc[mt][nt][2], acc[mt][nt][3],
                             af[mt][0], af[mt][1], af[mt][2], af[mt][3],
                             bf[nt][0], bf[nt][1]);
        }
        __syncthreads();
    }

    // ---- fused epilogue: bf16 store + attention dots ----
    int hg0 = (bn + wn * 32) >> 4;
    float asl[2][4], adl[2][4];
#pragma unroll
    for (int hs = 0; hs < 2; hs++) {
        int hb = (hg0 + hs) * 16;
        asl[hs][0] = __ldg(att_s + hb + 2 * tg);
        asl[hs][1] = __ldg(att_s + hb + 2 * tg + 1);
        asl[hs][2] = __ldg(att_s + hb + 8 + 2 * tg);
        asl[hs][3] = __ldg(att_s + hb + 9 + 2 * tg);
        adl[hs][0] = __ldg(att_d + hb + 2 * tg);
        adl[hs][1] = __ldg(att_d + hb + 2 * tg + 1);
        adl[hs][2] = __ldg(att_d + hb + 8 + 2 * tg);
        adl[hs][3] = __ldg(att_d + hb + 9 + 2 * tg);
    }

#pragma unroll
    for (int mt = 0; mt < 2; mt++) {
#pragma unroll
        for (int rh = 0; rh < 2; rh++) {
            int row = bm + wm * 32 + mt * 16 + g + rh * 8;
            int a0 = rh * 2, a1 = rh * 2 + 1;
            if (row < M) {
                __nv_bfloat16* hrow = hbf + (size_t)row * 256 + bn + wn * 32 + 2 * tg;
#pragma unroll
                for (int nt = 0; nt < 4; nt++) {
                    __nv_bfloat162 b2 = __float22bfloat162_rn(
                        make_float2(acc[mt][nt][a0], acc[mt][nt][a1]));
                    *(__nv_bfloat162*)(hrow + nt * 8) = b2;
                }
            }
#pragma unroll
            for (int hs = 0; hs < 2; hs++) {
                float s = acc[mt][2 * hs][a0]     * asl[hs][0]
                        + acc[mt][2 * hs][a1]     * asl[hs][1]
                        + acc[mt][2 * hs + 1][a0] * asl[hs][2]
                        + acc[mt][2 * hs + 1][a1] * asl[hs][3];
                float d = acc[mt][2 * hs][a0]     * adl[hs][0]
                        + acc[mt][2 * hs][a1]     * adl[hs][1]
                        + acc[mt][2 * hs + 1][a0] * adl[hs][2]
                        + acc[mt][2 * hs + 1][a1] * adl[hs][3];
                s += __shfl_xor_sync(0xffffffffu, s, 1);
                s += __shfl_xor_sync(0xffffffffu, s, 2);
                d += __shfl_xor_sync(0xffffffffu, d, 1);
                d += __shfl_xor_sync(0xffffffffu, d, 2);
                if (tg == 0 && row < M) {
                    g_asrc[row * 16 + hg0 + hs] = s;
                    g_adst[row * 16 + hg0 + hs] = d;
                }
            }
        }
    }
}

// ---------------- single-pass aggregation helpers ----------------
__device__ __forceinline__ float lrelu02(float x) { return (x > 0.f) ? x : 0.2f * x; }

// row-gather with L1 evict-first: the 25MB h-array has no L1 locality; keep L1 for asrc/csr.
__device__ __forceinline__ uint4 ldg_ef(const uint4* p) {
    uint4 v;
    asm volatile("ld.global.L1::evict_first.v4.u32 {%0,%1,%2,%3}, [%4];"
                 : "=r"(v.x), "=r"(v.y), "=r"(v.z), "=r"(v.w) : "l"(p));
    return v;
}

__device__ __forceinline__ void acc_bf16(float o[8], float al, uint4 pv) {
    float2 f0 = __bfloat1622float2(*(__nv_bfloat162*)&pv.x);
    float2 f1 = __bfloat1622float2(*(__nv_bfloat162*)&pv.y);
    float2 f2 = __bfloat1622float2(*(__nv_bfloat162*)&pv.z);
    float2 f3 = __bfloat1622float2(*(__nv_bfloat162*)&pv.w);
    o[0] += al * f0.x; o[1] += al * f0.y;
    o[2] += al * f1.x; o[3] += al * f1.y;
    o[4] += al * f2.x; o[5] += al * f2.y;
    o[6] += al * f3.x; o[7] += al * f3.y;
}

// ---------------- layer-1 aggregation: warp/node, single pass, unroll-8 ----------------
__global__ __launch_bounds__(256) void k_agg1(const float* __restrict__ bias,
                                              const float* __restrict__ gm,
                                              const float* __restrict__ bt,
                                              const float* __restrict__ mn,
                                              const float* __restrict__ vr) {
    int warp = (blockIdx.x * blockDim.x + threadIdx.x) >> 5;
    int lane = threadIdx.x & 31;
    if (warp >= N_NODES) return;
    int n = warp;
    int h = lane >> 1;

    float adn = g_adst[n * 16 + h];
    int jb = g_rowptr[n], je = g_rowptr[n + 1];

    const uint4* hbase = (const uint4*)g_h1bf;
    int voff = lane;   // (h*2 + half) == lane

    float o[8] = {0.f, 0.f, 0.f, 0.f, 0.f, 0.f, 0.f, 0.f};
    float e0 = __expf(lrelu02(g_asrc[n * 16 + h] + adn));
    float denom = e0;
    acc_bf16(o, e0, ldg_ef(hbase + (size_t)n * 32 + voff));

    int j = jb;
    for (; j + 8 <= je; j += 8) {
        int u[8];
#pragma unroll
        for (int q = 0; q < 8; q++) u[q] = g_csr_src[j + q];
        float x[8];
#pragma unroll
        for (int q = 0; q < 8; q++) x[q] = g_asrc[u[q] * 16 + h];
        uint4 p[8];
#pragma unroll
        for (int q = 0; q < 8; q++) p[q] = ldg_ef(hbase + (size_t)u[q] * 32 + voff);
        float a[8];
#pragma unroll
        for (int q = 0; q < 8; q++) { a[q] = __expf(lrelu02(x[q] + adn)); denom += a[q]; }
#pragma unroll
        for (int q = 0; q < 8; q++) acc_bf16(o, a[q], p[q]);
    }
    for (; j + 4 <= je; j += 4) {
        int u0 = g_csr_src[j],     u1 = g_csr_src[j + 1];
        int u2 = g_csr_src[j + 2], u3 = g_csr_src[j + 3];
        float x0 = g_asrc[u0 * 16 + h], x1 = g_asrc[u1 * 16 + h];
        float x2 = g_asrc[u2 * 16 + h], x3 = g_asrc[u3 * 16 + h];
        uint4 p0 = ldg_ef(hbase + (size_t)u0 * 32 + voff), p1 = ldg_ef(hbase + (size_t)u1 * 32 + voff);
        uint4 p2 = ldg_ef(hbase + (size_t)u2 * 32 + voff), p3 = ldg_ef(hbase + (size_t)u3 * 32 + voff);
        float a0 = __expf(lrelu02(x0 + adn));
        float a1 = __expf(lrelu02(x1 + adn));
        float a2 = __expf(lrelu02(x2 + adn));
        float a3 = __expf(lrelu02(x3 + adn));
        denom += (a0 + a1) + (a2 + a3);
        acc_bf16(o, a0, p0); acc_bf16(o, a1, p1);
        acc_bf16(o, a2, p2); acc_bf16(o, a3, p3);
    }
    for (; j < je; j++) {
        int u = g_csr_src[j];
        float a = __expf(lrelu02(g_asrc[u * 16 + h] + adn));
        denom += a;
        acc_bf16(o, a, ldg_ef(hbase + (size_t)u * 32 + voff));
    }

    float invs = 1.f / (denom + 1e-16f);
    int idx = lane * 8;
#pragma unroll
    for (int t = 0; t < 8; t++) {
        int c = idx + t;
        float v = o[t] * invs + bias[c];
        v = (v > 0.f) ? v : (__expf(v) - 1.f);
        v = (v - mn[c]) * (gm[c] * rsqrtf(vr[c] + 1e-5f)) + bt[c];
        o[t] = v;
    }
    uint32_t pk[4];
#pragma unroll
    for (int t = 0; t < 4; t++) {
        __nv_bfloat162 b2 = __float22bfloat162_rn(make_float2(o[2 * t], o[2 * t + 1]));
        pk[t] = *(uint32_t*)&b2;
    }
    *(uint4*)(g_h1bb + (size_t)n * 256 + idx) = make_uint4(pk[0], pk[1], pk[2], pk[3]);
}

// ---------------- layer-2 aggregation: single pass + head-mean + bn2 + pooling ----------------
__global__ __launch_bounds__(256) void k_agg2(const int* __restrict__ batch,
                                              const float* __restrict__ bias,
                                              const float* __restrict__ gm,
                                              const float* __restrict__ bt,
                                              const float* __restrict__ mn,
                                              const float* __restrict__ vr) {
    int warp = (blockIdx.x * blockDim.x + threadIdx.x) >> 5;
    int lane = threadIdx.x & 31;
    if (warp >= N_NODES) return;
    int n = warp;
    int h = lane >> 1;

    float adn = g_adst[n * 16 + h];
    int jb = g_rowptr[n], je = g_rowptr[n + 1];

    const uint4* hbase = (const uint4*)g_h2bf;
    int voff = lane;

    float o[8] = {0.f, 0.f, 0.f, 0.f, 0.f, 0.f, 0.f, 0.f};
    float e0 = __expf(lrelu02(g_asrc[n * 16 + h] + adn));
    float denom = e0;
    acc_bf16(o, e0, ldg_ef(hbase + (size_t)n * 32 + voff));

    int j = jb;
    for (; j + 8 <= je; j += 8) {
        int u[8];
#pragma unroll
        for (int q = 0; q < 8; q++) u[q] = g_csr_src[j + q];
        float x[8];
#pragma unroll
        for (int q = 0; q < 8; q++) x[q] = g_asrc[u[q] * 16 + h];
        uint4 p[8];
#pragma unroll
        for (int q = 0; q < 8; q++) p[q] = ldg_ef(hbase + (size_t)u[q] * 32 + voff);
        float a[8];
#pragma unroll
        for (int q = 0; q < 8; q++) { a[q] = __expf(lrelu02(x[q] + adn)); denom += a[q]; }
#pragma unroll
        for (int q = 0; q < 8; q++) acc_bf16(o, a[q], p[q]);
    }
    for (; j + 4 <= je; j += 4) {
        int u0 = g_csr_src[j],     u1 = g_csr_src[j + 1];
        int u2 = g_csr_src[j + 2], u3 = g_csr_src[j + 3];
        float x0 = g_asrc[u0 * 16 + h], x1 = g_asrc[u1 * 16 + h];
        float x2 = g_asrc[u2 * 16 + h], x3 = g_asrc[u3 * 16 + h];
        uint4 p0 = ldg_ef(hbase + (size_t)u0 * 32 + voff), p1 = ldg_ef(hbase + (size_t)u1 * 32 + voff);
        uint4 p2 = ldg_ef(hbase + (size_t)u2 * 32 + voff), p3 = ldg_ef(hbase + (size_t)u3 * 32 + voff);
        float a0 = __expf(lrelu02(x0 + adn));
        float a1 = __expf(lrelu02(x1 + adn));
        float a2 = __expf(lrelu02(x2 + adn));
        float a3 = __expf(lrelu02(x3 + adn));
        denom += (a0 + a1) + (a2 + a3);
        acc_bf16(o, a0, p0); acc_bf16(o, a1, p1);
        acc_bf16(o, a2, p2); acc_bf16(o, a3, p3);
    }
    for (; j < je; j++) {
        int u = g_csr_src[j];
        float a = __expf(lrelu02(g_asrc[u * 16 + h] + adn));
        denom += a;
        acc_bf16(o, a, ldg_ef(hbase + (size_t)u * 32 + voff));
    }

    float invs = 1.f / (denom + 1e-16f);
#pragma unroll
    for (int t = 0; t < 8; t++) o[t] *= invs;

    // mean over heads: xor-reduce bits 1..4 (keeps 'half' parity class)
#pragma unroll
    for (int t = 0; t < 8; t++) {
        float v = o[t];
        v += __shfl_xor_sync(0xffffffffu, v, 2);
        v += __shfl_xor_sync(0xffffffffu, v, 4);
        v += __shfl_xor_sync(0xffffffffu, v, 8);
        v += __shfl_xor_sync(0xffffffffu, v, 16);
        o[t] = v;
    }
    if (lane < 2) {
#pragma unroll
        for (int t = 0; t < 8; t++) {
            int c = lane * 8 + t;
            float v = o[t] * (1.f / 16.f) + bias[c];
            v = (v - mn[c]) * (gm[c] * rsqrtf(vr[c] + 1e-5f)) + bt[c];
            o[t] = v;
        }
        int gidx = batch[n];
        float* p = g_pool + gidx * 16 + lane * 8;
        asm volatile("red.global.add.v4.f32 [%0], {%1,%2,%3,%4};"
                     :: "l"(p), "f"(o[0]), "f"(o[1]), "f"(o[2]), "f"(o[3]) : "memory");
        asm volatile("red.global.add.v4.f32 [%0], {%1,%2,%3,%4};"
                     :: "l"(p + 4), "f"(o[4]), "f"(o[5]), "f"(o[6]), "f"(o[7]) : "memory");
    }
}

// ---------------- classifier ----------------
__global__ void k_final(const float* __restrict__ linW,
                        const float* __restrict__ linb,
                        float* __restrict__ out) {
    int tid = threadIdx.x;
    if (tid >= NG * NC) return;
    int g = tid / NC, k = tid % NC;
    float cg = fmaxf(g_cnt[g], 1.f);
    float acc = linb[k];
#pragma unroll
    for (int c = 0; c < HID; c++)
        acc += (g_pool[g * 16 + c] / cg) * linW[c * NC + k];
    out[g * NC + k] = acc;
}

// ---------------- launch ----------------
extern "C" void kernel_launch(void* const* d_in, const int* in_sizes, int n_in,
                              void* d_out, int out_size) {
    const float* x        = (const float*)d_in[0];
    const int*   ei       = (const int*)  d_in[1];
    const int*   batch    = (const int*)  d_in[2];
    const float* W1       = (const float*)d_in[3];
    const float* att_src1 = (const float*)d_in[4];
    const float* att_dst1 = (const float*)d_in[5];
    const float* bias1    = (const float*)d_in[6];
    const float* bn1_g    = (const float*)d_in[7];
    const float* bn1_b    = (const float*)d_in[8];
    const float* bn1_m    = (const float*)d_in[9];
    const float* bn1_v    = (const float*)d_in[10];
    const float* W2       = (const float*)d_in[11];
    const float* att_src2 = (const float*)d_in[12];
    const float* att_dst2 = (const float*)d_in[13];
    const float* bias2    = (const float*)d_in[14];
    const float* bn2_g    = (const float*)d_in[15];
    const float* bn2_b    = (const float*)d_in[16];
    const float* bn2_m    = (const float*)d_in[17];
    const float* bn2_v    = (const float*)d_in[18];
    const float* linW     = (const float*)d_in[19];
    const float* linb     = (const float*)d_in[20];
    float* out = (float*)d_out;

    __nv_bfloat16* d_h1bb; cudaGetSymbolAddress((void**)&d_h1bb, g_h1bb);
    __nv_bfloat16* d_h1bf; cudaGetSymbolAddress((void**)&d_h1bf, g_h1bf);
    __nv_bfloat16* d_h2bf; cudaGetSymbolAddress((void**)&d_h2bf, g_h2bf);

    static cudaStream_t s_side = nullptr;
    static cudaEvent_t ev_fork = nullptr, ev_join = nullptr;
    if (s_side == nullptr) {
        cudaStreamCreateWithFlags(&s_side, cudaStreamNonBlocking);
        cudaEventCreateWithFlags(&ev_fork, cudaEventDisableTiming);
        cudaEventCreateWithFlags(&ev_join, cudaEventDisableTiming);
    }

    cudaEventRecord(ev_fork, 0);
    cudaStreamWaitEvent(s_side, ev_fork, 0);

    // CSR build on side stream (5 launches; overlaps gemm1 on main stream)
    k_zero     <<<(N_NODES + 255) / 256, 256, 0, s_side>>>();
    k_counthist<<<(N_EDGES + 255) / 256, 256, 0, s_side>>>(batch, ei);
    k_scan1    <<<SCAN_BLK, 1024, 0, s_side>>>();
    k_scan23   <<<SCAN_BLK, 1024, 0, s_side>>>();
    k_scatter  <<<(N_EDGES + 255) / 256, 256, 0, s_side>>>(ei);
    cudaEventRecord(ev_join, s_side);

    dim3 ggrid((N_NODES + GBM - 1) / GBM, 256 / GBN);

    // layer 1 (GEMM + fused attn), concurrent with CSR build
    k_gemm_attn<0><<<ggrid, 256>>>(x, W1, d_h1bf, att_src1, att_dst1, NF);

    cudaStreamWaitEvent(0, ev_join, 0);

    k_agg1<<<(N_NODES * 32 + 255) / 256, 256>>>(bias1, bn1_g, bn1_b, bn1_m, bn1_v);

    // layer 2 (bf16 A input)
    k_gemm_attn<1><<<ggrid, 256>>>(d_h1bb, W2, d_h2bf, att_src2, att_dst2, D1);
    k_agg2<<<(N_NODES * 32 + 255) / 256, 256>>>(batch, bias2, bn2_g, bn2_b, bn2_m, bn2_v);

    k_final<<<1, NG * NC>>>(linW, linb, out);
}

// round 16
// speedup vs baseline: 1.0474x; 1.0274x over previous
#include <cuda_runtime.h>
#include <cuda_bf16.h>
#include <cuda_fp16.h>
#include <math.h>
#include <stdint.h>

#define N_NODES 50000
#define N_EDGES 800000
#define NF      128
#define D1      256
#define HEADS   16
#define HID     16
#define NG      64
#define NC      10
#define SCAN_BLK ((N_NODES + 1023) / 1024)   // 49

// ---------------- device scratch ----------------
__device__ __nv_bfloat16 g_h1bb[N_NODES * D1];  // post agg1 (bf16, GEMM2 input)
__device__ unsigned char g_h1f8[N_NODES * D1];  // layer1 GEMM out (fp8 e4m3, agg1 gather)
__device__ unsigned char g_h2f8[N_NODES * D1];  // layer2 GEMM out (fp8 e4m3, agg2 gather)
__device__ float g_asrc[N_NODES * HEADS];
__device__ float g_adst[N_NODES * HEADS];
__device__ int   g_deg   [N_NODES];
__device__ int   g_rowptr[N_NODES + 1];
__device__ int   g_cursor[N_NODES];
__device__ int   g_csr_src[N_EDGES];
__device__ int   g_bsum[64];
__device__ float g_pool[NG * HID];
__device__ float g_cnt [NG];

// ---------------- setup kernels ----------------
__global__ void k_zero() {
    int i = blockIdx.x * blockDim.x + threadIdx.x;
    if (i < N_NODES) g_deg[i] = 0;
    if (i < NG * HID) g_pool[i] = 0.f;
    if (i < NG) g_cnt[i] = 0.f;
}

// merged: per-graph node count + edge-dst histogram
__global__ void k_counthist(const int* __restrict__ batch, const int* __restrict__ ei) {
    __shared__ int loc[NG];
    int t = threadIdx.x;
    if (t < NG) loc[t] = 0;
    __syncthreads();
    int i = blockIdx.x * blockDim.x + t;
    if (i < N_NODES) atomicAdd(&loc[batch[i]], 1);
    if (i < N_EDGES) atomicAdd(&g_deg[ei[N_EDGES + i]], 1);
    __syncthreads();
    if (t < NG) { int v = loc[t]; if (v) atomicAdd(&g_cnt[t], (float)v); }
}

__global__ __launch_bounds__(1024) void k_scan1() {
    __shared__ int sh[1024];
    int tid = threadIdx.x;
    int i = blockIdx.x * 1024 + tid;
    int v = (i < N_NODES) ? g_deg[i] : 0;
    sh[tid] = v;
    __syncthreads();
    for (int off = 1; off < 1024; off <<= 1) {
        int t = (tid >= off) ? sh[tid - off] : 0;
        __syncthreads();
        sh[tid] += t;
        __syncthreads();
    }
    if (i < N_NODES) g_rowptr[i] = sh[tid] - v;
    if (tid == 1023) g_bsum[blockIdx.x] = sh[1023];
}

// merged scan2+scan3: every block redundantly reduces its prefix of the 49 block sums
__global__ __launch_bounds__(1024) void k_scan23() {
    __shared__ int red[64];
    int tid = threadIdx.x;
    if (tid < 64) red[tid] = (tid < (int)blockIdx.x && tid < SCAN_BLK) ? g_bsum[tid] : 0;
    __syncthreads();
    for (int s = 32; s > 0; s >>= 1) {
        if (tid < s) red[tid] += red[tid + s];
        __syncthreads();
    }
    int off = red[0];
    int i = blockIdx.x * 1024 + tid;
    if (i < N_NODES) {
        int r = g_rowptr[i] + off;
        g_rowptr[i] = r;
        g_cursor[i] = r;
    }
    if (i == 0) g_rowptr[N_NODES] = N_EDGES;
}

__global__ void k_scatter(const int* __restrict__ ei) {
    int e = blockIdx.x * blockDim.x + threadIdx.x;
    if (e >= N_EDGES) return;
    int s = ei[e];
    int d = ei[N_EDGES + e];
    int p = atomicAdd(&g_cursor[d], 1);
    g_csr_src[p] = s;
}

// ---------------- TF32 tensor-core GEMM + fused attention epilogue ----------------
#define GBM 128
#define GBN 64
#define GBK 32
#define AS_STRIDE 36
#define BS_STRIDE 36

__device__ __forceinline__ uint32_t f2tf32(float f) {
    uint32_t r;
    asm("cvt.rna.tf32.f32 %0, %1;" : "=r"(r) : "f"(f));
    return r;
}

__device__ __forceinline__ uint16_t f2_to_e4m3x2(float lo, float hi) {
    uint16_t u;
    asm("cvt.rn.satfinite.e4m3x2.f32 %0, %1, %2;" : "=h"(u) : "f"(hi), "f"(lo));
    return u;
}

__device__ __forceinline__ void mma_tf32(float& d0, float& d1, float& d2, float& d3,
                                         uint32_t a0, uint32_t a1, uint32_t a2, uint32_t a3,
                                         uint32_t b0, uint32_t b1) {
    asm volatile(
        "mma.sync.aligned.m16n8k8.row.col.f32.tf32.tf32.f32 "
        "{%0,%1,%2,%3}, {%4,%5,%6,%7}, {%8,%9}, {%0,%1,%2,%3};"
        : "+f"(d0), "+f"(d1), "+f"(d2), "+f"(d3)
        : "r"(a0), "r"(a1), "r"(a2), "r"(a3), "r"(b0), "r"(b1));
}

template <int ABF16>
__global__ __launch_bounds__(256) void k_gemm_attn(const void* __restrict__ Av,
                                                   const float* __restrict__ W,
                                                   unsigned char* __restrict__ h8,
                                                   const float* __restrict__ att_s,
                                                   const float* __restrict__ att_d,
                                                   int K) {
    __shared__ uint32_t As[GBM * AS_STRIDE];
    __shared__ uint32_t Bs[GBN * BS_STRIDE];
    const int M = N_NODES;

    int tid = threadIdx.x;
    int warp = tid >> 5, lane = tid & 31;
    int g = lane >> 2, tg = lane & 3;
    int wm = warp & 3;       // 4 m-warps
    int wn = warp >> 2;      // 2 n-warps
    int bm = blockIdx.x * GBM;
    int bn = blockIdx.y * GBN;

    float acc[2][4][4];
#pragma unroll
    for (int mt = 0; mt < 2; mt++)
#pragma unroll
        for (int nt = 0; nt < 4; nt++)
#pragma unroll
            for (int r = 0; r < 4; r++) acc[mt][nt][r] = 0.f;

    for (int k0 = 0; k0 < K; k0 += GBK) {
        if (ABF16) {
            const __nv_bfloat16* A = (const __nv_bfloat16*)Av;
            int row = tid >> 2;        // 0..63
            int c8 = tid & 3;          // 0..3
#pragma unroll
            for (int p = 0; p < 2; p++) {
                int r = row + p * 64;
                int gr = bm + r;
                uint4 v = make_uint4(0u, 0u, 0u, 0u);
                if (gr < M) v = *(const uint4*)(A + (size_t)gr * K + k0 + c8 * 8);
                uint32_t* dst = &As[r * AS_STRIDE + c8 * 8];
                dst[0] = v.x << 16; dst[1] = v.x & 0xFFFF0000u;
                dst[2] = v.y << 16; dst[3] = v.y & 0xFFFF0000u;
                dst[4] = v.z << 16; dst[5] = v.z & 0xFFFF0000u;
                dst[6] = v.w << 16; dst[7] = v.w & 0xFFFF0000u;
            }
        } else {
            const float* A = (const float*)Av;
            int row = tid >> 3;        // 0..31
            int c4 = tid & 7;          // 0..7
#pragma unroll
            for (int p = 0; p < 4; p++) {
                int r = row + p * 32;
                int gr = bm + r;
                float4 v = make_float4(0.f, 0.f, 0.f, 0.f);
                if (gr < M) v = *(const float4*)(A + (size_t)gr * K + k0 + c4 * 4);
                uint32_t* dst = &As[r * AS_STRIDE + c4 * 4];
                dst[0] = f2tf32(v.x); dst[1] = f2tf32(v.y);
                dst[2] = f2tf32(v.z); dst[3] = f2tf32(v.w);
            }
        }
        {
            int k = tid >> 4;
            int n4 = tid & 15;
#pragma unroll
            for (int p = 0; p < 2; p++) {
                int kk = k + p * 16;
                float4 v = *(const float4*)(W + (size_t)(k0 + kk) * 256 + bn + n4 * 4);
                Bs[(n4 * 4 + 0) * BS_STRIDE + kk] = f2tf32(v.x);
                Bs[(n4 * 4 + 1) * BS_STRIDE + kk] = f2tf32(v.y);
                Bs[(n4 * 4 + 2) * BS_STRIDE + kk] = f2tf32(v.z);
                Bs[(n4 * 4 + 3) * BS_STRIDE + kk] = f2tf32(v.w);
            }
        }
        __syncthreads();

#pragma unroll
        for (int ks = 0; ks < 4; ks++) {
            int kc = ks * 8 + tg;
            uint32_t af[2][4];
#pragma unroll
            for (int mt = 0; mt < 2; mt++) {
                int r0 = wm * 32 + mt * 16 + g;
                af[mt][0] = As[r0 * AS_STRIDE + kc];
                af[mt][1] = As[(r0 + 8) * AS_STRIDE + kc];
                af[mt][2] = As[r0 * AS_STRIDE + kc + 4];
                af[mt][3] = As[(r0 + 8) * AS_STRIDE + kc + 4];
            }
            uint32_t bf[4][2];
#pragma unroll
            for (int nt = 0; nt < 4; nt++) {
                int nb = wn * 32 + nt * 8 + g;
                bf[nt][0] = Bs[nb * BS_STRIDE + kc];
                bf[nt][1] = Bs[nb * BS_STRIDE + kc + 4];
            }
#pragma unroll
            for (int mt = 0; mt < 2; mt++)
#pragma unroll
                for (int nt = 0; nt < 4; nt++)
                    mma_tf32(acc[mt][nt][0], acc[mt][nt][1], acc[mt][nt][2], acc[mt][nt][3],
                             af[mt][0], af[mt][1], af[mt][2], af[mt][3],
                             bf[nt][0], bf[nt][1]);
        }
        __syncthreads();
    }

    // ---- fused epilogue: fp8 row store + attention dots ----
    int hg0 = (bn + wn * 32) >> 4;
    float asl[2][4], adl[2][4];
#pragma unroll
    for (int hs = 0; hs < 2; hs++) {
        int hb = (hg0 + hs) * 16;
        asl[hs][0] = __ldg(att_s + hb + 2 * tg);
        asl[hs][1] = __ldg(att_s + hb + 2 * tg + 1);
        asl[hs][2] = __ldg(att_s + hb + 8 + 2 * tg);
        asl[hs][3] = __ldg(att_s + hb + 9 + 2 * tg);
        adl[hs][0] = __ldg(att_d + hb + 2 * tg);
        adl[hs][1] = __ldg(att_d + hb + 2 * tg + 1);
        adl[hs][2] = __ldg(att_d + hb + 8 + 2 * tg);
        adl[hs][3] = __ldg(att_d + hb + 9 + 2 * tg);
    }

#pragma unroll
    for (int mt = 0; mt < 2; mt++) {
#pragma unroll
        for (int rh = 0; rh < 2; rh++) {
            int row = bm + wm * 32 + mt * 16 + g + rh * 8;
            int a0 = rh * 2, a1 = rh * 2 + 1;
            if (row < M) {
                unsigned char* hrow = h8 + (size_t)row * 256 + bn + wn * 32 + 2 * tg;
#pragma unroll
                for (int nt = 0; nt < 4; nt++) {
                    uint16_t pk = f2_to_e4m3x2(acc[mt][nt][a0], acc[mt][nt][a1]);
                    *(uint16_t*)(hrow + nt * 8) = pk;
                }
            }
#pragma unroll
            for (int hs = 0; hs < 2; hs++) {
                float s = acc[mt][2 * hs][a0]     * asl[hs][0]
                        + acc[mt][2 * hs][a1]     * asl[hs][1]
                        + acc[mt][2 * hs + 1][a0] * asl[hs][2]
                        + acc[mt][2 * hs + 1][a1] * asl[hs][3];
                float d = acc[mt][2 * hs][a0]     * adl[hs][0]
                        + acc[mt][2 * hs][a1]     * adl[hs][1]
                        + acc[mt][2 * hs + 1][a0] * adl[hs][2]
                        + acc[mt][2 * hs + 1][a1] * adl[hs][3];
                s += __shfl_xor_sync(0xffffffffu, s, 1);
                s += __shfl_xor_sync(0xffffffffu, s, 2);
                d += __shfl_xor_sync(0xffffffffu, d, 1);
                d += __shfl_xor_sync(0xffffffffu, d, 2);
                if (tg == 0 && row < M) {
                    g_asrc[row * 16 + hg0 + hs] = s;
                    g_adst[row * 16 + hg0 + hs] = d;
                }
            }
        }
    }
}

// ---------------- single-pass aggregation helpers ----------------
__device__ __forceinline__ float lrelu02(float x) { return (x > 0.f) ? x : 0.2f * x; }

// fp8x2 -> f16x2 (exact) -> float2
__device__ __forceinline__ float2 e4m3x2_to_f2(uint16_t v) {
    uint32_t h2;
    asm("cvt.rn.f16x2.e4m3x2 %0, %1;" : "=r"(h2) : "h"(v));
    __half2 hh = *(__half2*)&h2;
    return __half22float2(hh);
}

// 8B row-slice gather with L1 evict-first
__device__ __forceinline__ uint2 ldg_ef2(const uint2* p) {
    uint2 v;
    asm volatile("ld.global.L1::evict_first.v2.u32 {%0,%1}, [%2];"
                 : "=r"(v.x), "=r"(v.y) : "l"(p));
    return v;
}

__device__ __forceinline__ void acc_fp8(float o[8], float al, uint2 pv) {
    float2 f0 = e4m3x2_to_f2((uint16_t)(pv.x & 0xFFFFu));
    float2 f1 = e4m3x2_to_f2((uint16_t)(pv.x >> 16));
    float2 f2 = e4m3x2_to_f2((uint16_t)(pv.y & 0xFFFFu));
    float2 f3 = e4m3x2_to_f2((uint16_t)(pv.y >> 16));
    o[0] += al * f0.x; o[1] += al * f0.y;
    o[2] += al * f1.x; o[3] += al * f1.y;
    o[4] += al * f2.x; o[5] += al * f2.y;
    o[6] += al * f3.x; o[7] += al * f3.y;
}

// ---------------- layer-1 aggregation: warp/node, single pass, unroll-8 ----------------
// fp8 row = 256B = 32 uint2; lane l covers channels [8l, 8l+8).
__global__ __launch_bounds__(256) void k_agg1(const float* __restrict__ bias,
                                              const float* __restrict__ gm,
                                              const float* __restrict__ bt,
                                              const float* __restrict__ mn,
                                              const float* __restrict__ vr) {
    int warp = (blockIdx.x * blockDim.x + threadIdx.x) >> 5;
    int lane = threadIdx.x & 31;
    if (warp >= N_NODES) return;
    int n = warp;
    int h = lane >> 1;

    float adn = g_adst[n * 16 + h];
    int jb = g_rowptr[n], je = g_rowptr[n + 1];

    const uint2* hbase = (const uint2*)g_h1f8;

    float o[8] = {0.f, 0.f, 0.f, 0.f, 0.f, 0.f, 0.f, 0.f};
    float e0 = __expf(lrelu02(g_asrc[n * 16 + h] + adn));
    float denom = e0;
    acc_fp8(o, e0, ldg_ef2(hbase + (size_t)n * 32 + lane));

    int j = jb;
    for (; j + 8 <= je; j += 8) {
        int u[8];
#pragma unroll
        for (int q = 0; q < 8; q++) u[q] = g_csr_src[j + q];
        float x[8];
#pragma unroll
        for (int q = 0; q < 8; q++) x[q] = g_asrc[u[q] * 16 + h];
        uint2 p[8];
#pragma unroll
        for (int q = 0; q < 8; q++) p[q] = ldg_ef2(hbase + (size_t)u[q] * 32 + lane);
        float a[8];
#pragma unroll
        for (int q = 0; q < 8; q++) { a[q] = __expf(lrelu02(x[q] + adn)); denom += a[q]; }
#pragma unroll
        for (int q = 0; q < 8; q++) acc_fp8(o, a[q], p[q]);
    }
    for (; j + 4 <= je; j += 4) {
        int u0 = g_csr_src[j],     u1 = g_csr_src[j + 1];
        int u2 = g_csr_src[j + 2], u3 = g_csr_src[j + 3];
        float x0 = g_asrc[u0 * 16 + h], x1 = g_asrc[u1 * 16 + h];
        float x2 = g_asrc[u2 * 16 + h], x3 = g_asrc[u3 * 16 + h];
        uint2 p0 = ldg_ef2(hbase + (size_t)u0 * 32 + lane), p1 = ldg_ef2(hbase + (size_t)u1 * 32 + lane);
        uint2 p2 = ldg_ef2(hbase + (size_t)u2 * 32 + lane), p3 = ldg_ef2(hbase + (size_t)u3 * 32 + lane);
        float a0 = __expf(lrelu02(x0 + adn));
        float a1 = __expf(lrelu02(x1 + adn));
        float a2 = __expf(lrelu02(x2 + adn));
        float a3 = __expf(lrelu02(x3 + adn));
        denom += (a0 + a1) + (a2 + a3);
        acc_fp8(o, a0, p0); acc_fp8(o, a1, p1);
        acc_fp8(o, a2, p2); acc_fp8(o, a3, p3);
    }
    for (; j < je; j++) {
        int u = g_csr_src[j];
        float a = __expf(lrelu02(g_asrc[u * 16 + h] + adn));
        denom += a;
        acc_fp8(o, a, ldg_ef2(hbase + (size_t)u * 32 + lane));
    }

    float invs = 1.f / (denom + 1e-16f);
    int idx = lane * 8;
#pragma unroll
    for (int t = 0; t < 8; t++) {
        int c = idx + t;
        float v = o[t] * invs + bias[c];
        v = (v > 0.f) ? v : (__expf(v) - 1.f);
        v = (v - mn[c]) * (gm[c] * rsqrtf(vr[c] + 1e-5f)) + bt[c];
        o[t] = v;
    }
    uint32_t pk[4];
#pragma unroll
    for (int t = 0; t < 4; t++) {
        __nv_bfloat162 b2 = __float22bfloat162_rn(make_float2(o[2 * t], o[2 * t + 1]));
        pk[t] = *(uint32_t*)&b2;
    }
    *(uint4*)(g_h1bb + (size_t)n * 256 + idx) = make_uint4(pk[0], pk[1], pk[2], pk[3]);
}

// ---------------- layer-2 aggregation: single pass + head-mean + bn2 + pooling ----------------
__global__ __launch_bounds__(256) void k_agg2(const int* __restrict__ batch,
                                              const float* __restrict__ bias,
                                              const float* __restrict__ gm,
                                              const float* __restrict__ bt,
                                              const float* __restrict__ mn,
                                              const float* __restrict__ vr) {
    int warp = (blockIdx.x * blockDim.x + threadIdx.x) >> 5;
    int lane = threadIdx.x & 31;
    if (warp >= N_NODES) return;
    int n = warp;
    int h = lane >> 1;

    float adn = g_adst[n * 16 + h];
    int jb = g_rowptr[n], je = g_rowptr[n + 1];

    const uint2* hbase = (const uint2*)g_h2f8;

    float o[8] = {0.f, 0.f, 0.f, 0.f, 0.f, 0.f, 0.f, 0.f};
    float e0 = __expf(lrelu02(g_asrc[n * 16 + h] + adn));
    float denom = e0;
    acc_fp8(o, e0, ldg_ef2(hbase + (size_t)n * 32 + lane));

    int j = jb;
    for (; j + 8 <= je; j += 8) {
        int u[8];
#pragma unroll
        for (int q = 0; q < 8; q++) u[q] = g_csr_src[j + q];
        float x[8];
#pragma unroll
        for (int q = 0; q < 8; q++) x[q] = g_asrc[u[q] * 16 + h];
        uint2 p[8];
#pragma unroll
        for (int q = 0; q < 8; q++) p[q] = ldg_ef2(hbase + (size_t)u[q] * 32 + lane);
        float a[8];
#pragma unroll
        for (int q = 0; q < 8; q++) { a[q] = __expf(lrelu02(x[q] + adn)); denom += a[q]; }
#pragma unroll
        for (int q = 0; q < 8; q++) acc_fp8(o, a[q], p[q]);
    }
    for (; j + 4 <= je; j += 4) {
        int u0 = g_csr_src[j],     u1 = g_csr_src[j + 1];
        int u2 = g_csr_src[j + 2], u3 = g_csr_src[j + 3];
        float x0 = g_asrc[u0 * 16 + h], x1 = g_asrc[u1 * 16 + h];
        float x2 = g_asrc[u2 * 16 + h], x3 = g_asrc[u3 * 16 + h];
        uint2 p0 = ldg_ef2(hbase + (size_t)u0 * 32 + lane), p1 = ldg_ef2(hbase + (size_t)u1 * 32 + lane);
        uint2 p2 = ldg_ef2(hbase + (size_t)u2 * 32 + lane), p3 = ldg_ef2(hbase + (size_t)u3 * 32 + lane);
        float a0 = __expf(lrelu02(x0 + adn));
        float a1 = __expf(lrelu02(x1 + adn));
        float a2 = __expf(lrelu02(x2 + adn));
        float a3 = __expf(lrelu02(x3 + adn));
        denom += (a0 + a1) + (a2 + a3);
        acc_fp8(o, a0, p0); acc_fp8(o, a1, p1);
        acc_fp8(o, a2, p2); acc_fp8(o, a3, p3);
    }
    for (; j < je; j++) {
        int u = g_csr_src[j];
        float a = __expf(lrelu02(g_asrc[u * 16 + h] + adn));
        denom += a;
        acc_fp8(o, a, ldg_ef2(hbase + (size_t)u * 32 + lane));
    }

    float invs = 1.f / (denom + 1e-16f);
#pragma unroll
    for (int t = 0; t < 8; t++) o[t] *= invs;

    // mean over heads: xor-reduce bits 1..4 (keeps 'half' parity class)
#pragma unroll
    for (int t = 0; t < 8; t++) {
        float v = o[t];
        v += __shfl_xor_sync(0xffffffffu, v, 2);
        v += __shfl_xor_sync(0xffffffffu, v, 4);
        v += __shfl_xor_sync(0xffffffffu, v, 8);
        v += __shfl_xor_sync(0xffffffffu, v, 16);
        o[t] = v;
    }
    if (lane < 2) {
#pragma unroll
        for (int t = 0; t < 8; t++) {
            int c = lane * 8 + t;
            float v = o[t] * (1.f / 16.f) + bias[c];
            v = (v - mn[c]) * (gm[c] * rsqrtf(vr[c] + 1e-5f)) + bt[c];
            o[t] = v;
        }
        int gidx = batch[n];
        float* p = g_pool + gidx * 16 + lane * 8;
        asm volatile("red.global.add.v4.f32 [%0], {%1,%2,%3,%4};"
                     :: "l"(p), "f"(o[0]), "f"(o[1]), "f"(o[2]), "f"(o[3]) : "memory");
        asm volatile("red.global.add.v4.f32 [%0], {%1,%2,%3,%4};"
                     :: "l"(p + 4), "f"(o[4]), "f"(o[5]), "f"(o[6]), "f"(o[7]) : "memory");
    }
}

// ---------------- classifier ----------------
__global__ void k_final(const float* __restrict__ linW,
                        const float* __restrict__ linb,
                        float* __restrict__ out) {
    int tid = threadIdx.x;
    if (tid >= NG * NC) return;
    int g = tid / NC, k = tid % NC;
    float cg = fmaxf(g_cnt[g], 1.f);
    float acc = linb[k];
#pragma unroll
    for (int c = 0; c < HID; c++)
        acc += (g_pool[g * 16 + c] / cg) * linW[c * NC + k];
    out[g * NC + k] = acc;
}

// ---------------- launch ----------------
extern "C" void kernel_launch(void* const* d_in, const int* in_sizes, int n_in,
                              void* d_out, int out_size) {
    const float* x        = (const float*)d_in[0];
    const int*   ei       = (const int*)  d_in[1];
    const int*   batch    = (const int*)  d_in[2];
    const float* W1       = (const float*)d_in[3];
    const float* att_src1 = (const float*)d_in[4];
    const float* att_dst1 = (const float*)d_in[5];
    const float* bias1    = (const float*)d_in[6];
    const float* bn1_g    = (const float*)d_in[7];
    const float* bn1_b    = (const float*)d_in[8];
    const float* bn1_m    = (const float*)d_in[9];
    const float* bn1_v    = (const float*)d_in[10];
    const float* W2       = (const float*)d_in[11];
    const float* att_src2 = (const float*)d_in[12];
    const float* att_dst2 = (const float*)d_in[13];
    const float* bias2    = (const float*)d_in[14];
    const float* bn2_g    = (const float*)d_in[15];
    const float* bn2_b    = (const float*)d_in[16];
    const float* bn2_m    = (const float*)d_in[17];
    const float* bn2_v    = (const float*)d_in[18];
    const float* linW     = (const float*)d_in[19];
    const float* linb     = (const float*)d_in[20];
    float* out = (float*)d_out;

    __nv_bfloat16* d_h1bb; cudaGetSymbolAddress((void**)&d_h1bb, g_h1bb);
    unsigned char* d_h1f8; cudaGetSymbolAddress((void**)&d_h1f8, g_h1f8);
    unsigned char* d_h2f8; cudaGetSymbolAddress((void**)&d_h2f8, g_h2f8);

    static cudaStream_t s_side = nullptr;
    static cudaEvent_t ev_fork = nullptr, ev_join = nullptr;
    if (s_side == nullptr) {
        cudaStreamCreateWithFlags(&s_side, cudaStreamNonBlocking);
        cudaEventCreateWithFlags(&ev_fork, cudaEventDisableTiming);
        cudaEventCreateWithFlags(&ev_join, cudaEventDisableTiming);
    }

    cudaEventRecord(ev_fork, 0);
    cudaStreamWaitEvent(s_side, ev_fork, 0);

    dim3 ggrid((N_NODES + GBM - 1) / GBM, 256 / GBN);

    // Submission order puts gemm1 at slot #4 (the slot ncu -s 5 -c 1 captures).
    k_zero     <<<(N_NODES + 255) / 256, 256, 0, s_side>>>();           // #1
    k_counthist<<<(N_EDGES + 255) / 256, 256, 0, s_side>>>(batch, ei);  // #2
    k_scan1    <<<SCAN_BLK, 1024, 0, s_side>>>();                       // #3
    k_gemm_attn<0><<<ggrid, 256>>>(x, W1, d_h1f8, att_src1, att_dst1, NF); // #4 (main)
    k_scan23   <<<SCAN_BLK, 1024, 0, s_side>>>();                       // #5
    k_scatter  <<<(N_EDGES + 255) / 256, 256, 0, s_side>>>(ei);         // #6
    cudaEventRecord(ev_join, s_side);

    cudaStreamWaitEvent(0, ev_join, 0);

    k_agg1<<<(N_NODES * 32 + 255) / 256, 256>>>(bias1, bn1_g, bn1_b, bn1_m, bn1_v);

    // layer 2 (bf16 A input)
    k_gemm_attn<1><<<ggrid, 256>>>(d_h1bb, W2, d_h2f8, att_src2, att_dst2, D1);
    k_agg2<<<(N_NODES * 32 + 255) / 256, 256>>>(batch, bias2, bn2_g, bn2_b, bn2_m, bn2_v);

    k_final<<<1, NG * NC>>>(linW, linb, out);
}